// round 1
// baseline (speedup 1.0000x reference)
#include <cuda_runtime.h>
#include <cstddef>

#define FD 32
#define HD 64
#define ED 128

// Zero-init the output: segment max of ReLU outputs (>=0) with 0 init
// reproduces jnp.where(isfinite(segmax), segmax, 0).
__global__ void init_out_kernel(float* __restrict__ out, int n) {
    int i = blockIdx.x * blockDim.x + threadIdx.x;
    if (i < n) out[i] = 0.0f;
}

__global__ __launch_bounds__(256, 2) void mlp_segmax_kernel(
    const float* __restrict__ X,        // [N, 32]
    const int*   __restrict__ seg,      // [N]
    const float* __restrict__ W1,       // [32, 64]
    const float* __restrict__ b1,       // [64]
    const float* __restrict__ W2,       // [64, 128]
    const float* __restrict__ b2,       // [128]
    unsigned*    __restrict__ out,      // [NSEG, 128] viewed as uint bits
    int n)
{
    __shared__ float sW1[FD * HD];   // 8 KB
    __shared__ float sW2[HD * ED];   // 32 KB
    __shared__ float sb1[HD];
    __shared__ float sb2[ED];

    for (int i = threadIdx.x; i < FD * HD; i += 256) sW1[i] = W1[i];
    for (int i = threadIdx.x; i < HD * ED; i += 256) sW2[i] = W2[i];
    if (threadIdx.x < HD) sb1[threadIdx.x] = b1[threadIdx.x];
    if (threadIdx.x < ED) sb2[threadIdx.x] = b2[threadIdx.x];
    __syncthreads();

    int p = blockIdx.x * 256 + threadIdx.x;
    if (p >= n) return;

    // ---- load point features (8x LDG.128) ----
    float x[FD];
    {
        const float4* xr = reinterpret_cast<const float4*>(X) + (size_t)p * (FD / 4);
        #pragma unroll
        for (int i = 0; i < FD / 4; i++) {
            float4 v = __ldg(xr + i);
            x[4 * i + 0] = v.x; x[4 * i + 1] = v.y;
            x[4 * i + 2] = v.z; x[4 * i + 3] = v.w;
        }
    }

    // ---- layer 1: h = relu(x @ W1 + b1), h kept in registers ----
    float h[HD];
    #pragma unroll
    for (int j = 0; j < HD; j += 4) {
        float4 acc = *reinterpret_cast<const float4*>(sb1 + j);
        #pragma unroll
        for (int k = 0; k < FD; k++) {
            float4 w = *reinterpret_cast<const float4*>(sW1 + k * HD + j);
            acc.x = fmaf(x[k], w.x, acc.x);
            acc.y = fmaf(x[k], w.y, acc.y);
            acc.z = fmaf(x[k], w.z, acc.z);
            acc.w = fmaf(x[k], w.w, acc.w);
        }
        h[j + 0] = fmaxf(acc.x, 0.0f);
        h[j + 1] = fmaxf(acc.y, 0.0f);
        h[j + 2] = fmaxf(acc.z, 0.0f);
        h[j + 3] = fmaxf(acc.w, 0.0f);
    }

    // ---- layer 2 + segment max epilogue ----
    int s = seg[p];
    unsigned* ob = out + (size_t)s * ED;

    #pragma unroll 1   // keep code size bounded; inner k fully unrolled for static h[k]
    for (int j = 0; j < ED; j += 4) {
        float4 acc = *reinterpret_cast<const float4*>(sb2 + j);
        #pragma unroll
        for (int k = 0; k < HD; k++) {
            float4 w = *reinterpret_cast<const float4*>(sW2 + k * ED + j);
            acc.x = fmaf(h[k], w.x, acc.x);
            acc.y = fmaf(h[k], w.y, acc.y);
            acc.z = fmaf(h[k], w.z, acc.z);
            acc.w = fmaf(h[k], w.w, acc.w);
        }
        // ReLU outputs are >= 0: uint bit pattern is order-preserving, and the
        // init value 0u == 0.0f. Skip atomics for zeros (~half of them).
        unsigned v0 = __float_as_uint(fmaxf(acc.x, 0.0f));
        unsigned v1 = __float_as_uint(fmaxf(acc.y, 0.0f));
        unsigned v2 = __float_as_uint(fmaxf(acc.z, 0.0f));
        unsigned v3 = __float_as_uint(fmaxf(acc.w, 0.0f));
        if (v0) atomicMax(ob + j + 0, v0);
        if (v1) atomicMax(ob + j + 1, v1);
        if (v2) atomicMax(ob + j + 2, v2);
        if (v3) atomicMax(ob + j + 3, v3);
    }
}

extern "C" void kernel_launch(void* const* d_in, const int* in_sizes, int n_in,
                              void* d_out, int out_size)
{
    const float* X   = (const float*)d_in[0];
    const int*   seg = (const int*)  d_in[1];
    const float* W1  = (const float*)d_in[2];
    const float* b1  = (const float*)d_in[3];
    const float* W2  = (const float*)d_in[4];
    const float* b2  = (const float*)d_in[5];
    float* out = (float*)d_out;

    int n = in_sizes[1];               // number of points (index count)

    init_out_kernel<<<(out_size + 255) / 256, 256>>>(out, out_size);
    mlp_segmax_kernel<<<(n + 255) / 256, 256>>>(
        X, seg, W1, b1, W2, b2, (unsigned*)out, n);
}

// round 2
// speedup vs baseline: 1.1749x; 1.1749x over previous
#include <cuda_runtime.h>
#include <cstddef>

#define FD 32
#define HD 64
#define ED 128

typedef unsigned long long ull;

__device__ __forceinline__ ull ffma2(ull a, ull b, ull c) {
    ull d;
    asm("fma.rn.f32x2 %0, %1, %2, %3;" : "=l"(d) : "l"(a), "l"(b), "l"(c));
    return d;
}
__device__ __forceinline__ float f2sum(ull a) {
    float lo, hi;
    asm("mov.b64 {%0, %1}, %2;" : "=f"(lo), "=f"(hi) : "l"(a));
    return lo + hi;
}
__device__ __forceinline__ ull fpack(float lo, float hi) {
    ull d;
    asm("mov.b64 %0, {%1, %2};" : "=l"(d) : "f"(lo), "f"(hi));
    return d;
}

// Zero-init output: segment-max of ReLU outputs (>=0) with 0 init reproduces
// jnp.where(isfinite(segmax), segmax, 0).
__global__ void init_out_kernel(float* __restrict__ out, int n) {
    int i = blockIdx.x * blockDim.x + threadIdx.x;
    if (i < n) out[i] = 0.0f;
}

// 128 threads/block, 2 points per thread (256 points/block).
__global__ __launch_bounds__(128) void mlp_segmax_kernel(
    const float* __restrict__ X,        // [N, 32]
    const int*   __restrict__ seg,      // [N]
    const float* __restrict__ W1,       // [32, 64]
    const float* __restrict__ b1,       // [64]
    const float* __restrict__ W2,       // [64, 128]
    const float* __restrict__ b2,       // [128]
    unsigned*    __restrict__ out,      // [NSEG, 128] as uint bits
    int n)
{
    // Transposed, K-contiguous weight layouts: one LDS.128 on a row j yields
    // weights for 4 consecutive k = two f32x2 operands, no packing needed.
    __shared__ float sW1T[HD * FD];   // [j=64][k=32], 8 KB, rows 128B-aligned
    __shared__ float sW2T[ED * HD];   // [j=128][k=64], 32 KB, rows 256B-aligned
    __shared__ float sb1[HD];
    __shared__ float sb2[ED];

    int t = threadIdx.x;
    for (int i = t; i < FD * HD; i += 128)
        sW1T[(i & (HD - 1)) * FD + (i >> 6)] = W1[i];     // i = k*64 + j
    for (int i = t; i < HD * ED; i += 128)
        sW2T[(i & (ED - 1)) * HD + (i >> 7)] = W2[i];     // i = k*128 + j
    if (t < HD) sb1[t] = b1[t];
    sb2[t] = b2[t];
    if (t + 64 < ED) sb2[t + 64] = b2[t + 64];            // t covers 0..127 anyway
    __syncthreads();

    int base = blockIdx.x * 256;
    int p0 = base + t;
    int p1 = base + 128 + t;
    bool v0 = p0 < n, v1 = p1 < n;
    int q0 = v0 ? p0 : 0;
    int q1 = v1 ? p1 : 0;

    // ---- load features, naturally K-pair-packed (u64 = 2 consecutive floats)
    ull xx0[FD / 2], xx1[FD / 2];
    {
        const ulonglong2* xr0 = reinterpret_cast<const ulonglong2*>(X + (size_t)q0 * FD);
        const ulonglong2* xr1 = reinterpret_cast<const ulonglong2*>(X + (size_t)q1 * FD);
        #pragma unroll
        for (int i = 0; i < FD / 4; i++) {
            ulonglong2 a = __ldg(xr0 + i);
            xx0[2 * i] = a.x; xx0[2 * i + 1] = a.y;
            ulonglong2 b = __ldg(xr1 + i);
            xx1[2 * i] = b.x; xx1[2 * i + 1] = b.y;
        }
    }

    // ---- layer 1: hh = relu(x @ W1 + b1), outputs packed in j-pairs ----
    ull hh0[HD / 2], hh1[HD / 2];
    #pragma unroll
    for (int j2 = 0; j2 < HD / 2; j2++) {
        const float* r = sW1T + (2 * j2) * FD;
        ull a00 = 0, a01 = 0, a10 = 0, a11 = 0;   // (point, output) partials over even/odd k
        #pragma unroll
        for (int q = 0; q < FD / 4; q++) {
            ulonglong2 wA = *reinterpret_cast<const ulonglong2*>(r + 4 * q);        // row j
            ulonglong2 wB = *reinterpret_cast<const ulonglong2*>(r + FD + 4 * q);   // row j+1
            a00 = ffma2(xx0[2 * q], wA.x, a00); a00 = ffma2(xx0[2 * q + 1], wA.y, a00);
            a01 = ffma2(xx0[2 * q], wB.x, a01); a01 = ffma2(xx0[2 * q + 1], wB.y, a01);
            a10 = ffma2(xx1[2 * q], wA.x, a10); a10 = ffma2(xx1[2 * q + 1], wA.y, a10);
            a11 = ffma2(xx1[2 * q], wB.x, a11); a11 = ffma2(xx1[2 * q + 1], wB.y, a11);
        }
        float bA = sb1[2 * j2], bB = sb1[2 * j2 + 1];
        hh0[j2] = fpack(fmaxf(f2sum(a00) + bA, 0.f), fmaxf(f2sum(a01) + bB, 0.f));
        hh1[j2] = fpack(fmaxf(f2sum(a10) + bA, 0.f), fmaxf(f2sum(a11) + bB, 0.f));
    }

    // ---- layer 2 + segment-max epilogue ----
    int s0 = __ldg(seg + q0);
    int s1 = __ldg(seg + q1);
    unsigned* ob0 = out + (size_t)s0 * ED;
    unsigned* ob1 = out + (size_t)s1 * ED;

    #pragma unroll 1   // bound code size; hh indices inside stay compile-time constant
    for (int j = 0; j < ED; j += 2) {
        const float* r = sW2T + j * HD;
        ull a00 = 0, a01 = 0, a10 = 0, a11 = 0;
        #pragma unroll
        for (int q = 0; q < HD / 4; q++) {
            ulonglong2 wA = *reinterpret_cast<const ulonglong2*>(r + 4 * q);        // row j
            ulonglong2 wB = *reinterpret_cast<const ulonglong2*>(r + HD + 4 * q);   // row j+1
            a00 = ffma2(hh0[2 * q], wA.x, a00); a00 = ffma2(hh0[2 * q + 1], wA.y, a00);
            a01 = ffma2(hh0[2 * q], wB.x, a01); a01 = ffma2(hh0[2 * q + 1], wB.y, a01);
            a10 = ffma2(hh1[2 * q], wA.x, a10); a10 = ffma2(hh1[2 * q + 1], wA.y, a10);
            a11 = ffma2(hh1[2 * q], wB.x, a11); a11 = ffma2(hh1[2 * q + 1], wB.y, a11);
        }
        float bA = sb2[j], bB = sb2[j + 1];
        // ReLU outputs >= 0: uint bit pattern is order-preserving; init 0u == 0.0f.
        // Skip atomics for zeros (~half).
        unsigned u00 = __float_as_uint(fmaxf(f2sum(a00) + bA, 0.f));
        unsigned u01 = __float_as_uint(fmaxf(f2sum(a01) + bB, 0.f));
        unsigned u10 = __float_as_uint(fmaxf(f2sum(a10) + bA, 0.f));
        unsigned u11 = __float_as_uint(fmaxf(f2sum(a11) + bB, 0.f));
        if (v0 && u00) atomicMax(ob0 + j, u00);
        if (v0 && u01) atomicMax(ob0 + j + 1, u01);
        if (v1 && u10) atomicMax(ob1 + j, u10);
        if (v1 && u11) atomicMax(ob1 + j + 1, u11);
    }
}

extern "C" void kernel_launch(void* const* d_in, const int* in_sizes, int n_in,
                              void* d_out, int out_size)
{
    const float* X   = (const float*)d_in[0];
    const int*   seg = (const int*)  d_in[1];
    const float* W1  = (const float*)d_in[2];
    const float* b1  = (const float*)d_in[3];
    const float* W2  = (const float*)d_in[4];
    const float* b2  = (const float*)d_in[5];
    float* out = (float*)d_out;

    int n = in_sizes[1];   // number of points

    init_out_kernel<<<(out_size + 255) / 256, 256>>>(out, out_size);
    int blocks = (n + 255) / 256;
    mlp_segmax_kernel<<<blocks, 128>>>(X, seg, W1, b1, W2, b2, (unsigned*)out, n);
}

// round 3
// speedup vs baseline: 1.3788x; 1.1736x over previous
#include <cuda_runtime.h>
#include <cstddef>

#define FD 32
#define HD 64
#define ED 128
#define MT 128   // points per CTA tile

typedef unsigned long long ull;

__device__ __forceinline__ ull ffma2(ull a, ull b, ull c) {
    ull d;
    asm("fma.rn.f32x2 %0, %1, %2, %3;" : "=l"(d) : "l"(a), "l"(b), "l"(c));
    return d;
}
__device__ __forceinline__ ull fdup(float x) {
    ull d;
    asm("mov.b64 %0, {%1, %1};" : "=l"(d) : "f"(x));
    return d;
}
__device__ __forceinline__ void funpack(ull a, float& lo, float& hi) {
    asm("mov.b64 {%0, %1}, %2;" : "=f"(lo), "=f"(hi) : "l"(a));
}

// Zero-init output: segment-max of ReLU outputs (>=0) with 0 init reproduces
// jnp.where(isfinite(segmax), segmax, 0).
__global__ void init_out_kernel(float* __restrict__ out, int n) {
    int i = blockIdx.x * blockDim.x + threadIdx.x;
    if (i < n) out[i] = 0.0f;
}

// 256 threads, one 128-point tile per CTA.
// Thread grid: jb = t%16 (j-blocks), mb = t/16 (m-blocks).
// GEMM1: thread tile 8m x 4j (j = jb*4..);  GEMM2: 8m x 8j (j = jb*8..).
__global__ __launch_bounds__(256, 2) void fused_mlp_segmax(
    const float* __restrict__ X,        // [N, 32]
    const int*   __restrict__ seg,      // [N]
    const float* __restrict__ W1,       // [32, 64]  (k-major, j contiguous)
    const float* __restrict__ b1,       // [64]
    const float* __restrict__ W2,       // [64, 128] (k-major, j contiguous)
    const float* __restrict__ b2,       // [128]
    unsigned*    __restrict__ out,      // [NSEG, 128] as uint bits
    int n)
{
    __shared__ float sW1[FD * HD];      // [k][j], 8 KB
    __shared__ float sHX[HD * MT];      // H: [j<64][m<128], 32 KB; X aliased in rows 0..31
    __shared__ float sb1[HD];
    __shared__ float sb2[ED];
    __shared__ int   sseg[MT];

    int t = threadIdx.x;
    int tile = blockIdx.x * MT;

    // ---- stage W1 (direct layout), biases, seg ids ----
    {
        const float4* W1g4 = reinterpret_cast<const float4*>(W1);
        float4* sW14 = reinterpret_cast<float4*>(sW1);
        sW14[t]       = __ldg(W1g4 + t);
        sW14[t + 256] = __ldg(W1g4 + t + 256);
    }
    if (t < HD) sb1[t] = b1[t];
    if (t < ED) sb2[t] = b2[t];
    if (t < MT) sseg[t] = __ldg(seg + min(tile + t, n - 1));

    // ---- stage X transposed into sHX[k][m] (rows 0..31) ----
    {
        int m  = t >> 1;
        int kh = (t & 1) * 16;
        int p  = min(tile + m, n - 1);
        const float4* xr = reinterpret_cast<const float4*>(X + (size_t)p * FD) + (kh >> 2);
        #pragma unroll
        for (int i = 0; i < 4; i++) {
            float4 v = __ldg(xr + i);
            int k = kh + 4 * i;
            sHX[(k + 0) * MT + m] = v.x;
            sHX[(k + 1) * MT + m] = v.y;
            sHX[(k + 2) * MT + m] = v.z;
            sHX[(k + 3) * MT + m] = v.w;
        }
    }
    __syncthreads();

    int jb = t & 15;
    int mb = t >> 4;

    // ================= GEMM1: H = relu(X @ W1 + b1) =================
    ull acc1[8][2];
    #pragma unroll
    for (int mi = 0; mi < 8; mi++) { acc1[mi][0] = 0ull; acc1[mi][1] = 0ull; }

    #pragma unroll
    for (int k = 0; k < FD; k++) {
        ulonglong2 w = *reinterpret_cast<const ulonglong2*>(sW1 + k * HD + jb * 4);
        const float4* xr = reinterpret_cast<const float4*>(sHX + k * MT + mb * 8);
        float4 x0 = xr[0], x1 = xr[1];
        float xs[8] = {x0.x, x0.y, x0.z, x0.w, x1.x, x1.y, x1.z, x1.w};
        #pragma unroll
        for (int mi = 0; mi < 8; mi++) {
            ull d = fdup(xs[mi]);
            acc1[mi][0] = ffma2(d, w.x, acc1[mi][0]);
            acc1[mi][1] = ffma2(d, w.y, acc1[mi][1]);
        }
    }

    float h[8][4];
    {
        float bb0 = sb1[jb * 4 + 0], bb1 = sb1[jb * 4 + 1];
        float bb2v = sb1[jb * 4 + 2], bb3 = sb1[jb * 4 + 3];
        #pragma unroll
        for (int mi = 0; mi < 8; mi++) {
            float a, b;
            funpack(acc1[mi][0], a, b);
            h[mi][0] = fmaxf(a + bb0, 0.f);
            h[mi][1] = fmaxf(b + bb1, 0.f);
            funpack(acc1[mi][1], a, b);
            h[mi][2] = fmaxf(a + bb2v, 0.f);
            h[mi][3] = fmaxf(b + bb3, 0.f);
        }
    }
    __syncthreads();   // all X reads complete before H overwrites the region

    // store H into sHX[j][m]
    #pragma unroll
    for (int ji = 0; ji < 4; ji++) {
        int j = jb * 4 + ji;
        *reinterpret_cast<float4*>(sHX + j * MT + mb * 8) =
            make_float4(h[0][ji], h[1][ji], h[2][ji], h[3][ji]);
        *reinterpret_cast<float4*>(sHX + j * MT + mb * 8 + 4) =
            make_float4(h[4][ji], h[5][ji], h[6][ji], h[7][ji]);
    }
    __syncthreads();

    // ================= GEMM2: O = relu(H @ W2 + b2) =================
    ull acc[8][4];
    #pragma unroll
    for (int mi = 0; mi < 8; mi++)
        #pragma unroll
        for (int jp = 0; jp < 4; jp++) acc[mi][jp] = 0ull;

    const ulonglong2* W2g = reinterpret_cast<const ulonglong2*>(W2);
    #pragma unroll 8
    for (int k = 0; k < HD; k++) {
        // weights for 8 j's = 4 j-pairs, contiguous: 2x LDG.128 (L1-resident)
        ulonglong2 wA = __ldg(W2g + (size_t)k * (ED / 4) + jb * 2);
        ulonglong2 wB = __ldg(W2g + (size_t)k * (ED / 4) + jb * 2 + 1);
        const float4* xr = reinterpret_cast<const float4*>(sHX + k * MT + mb * 8);
        float4 x0 = xr[0], x1 = xr[1];
        float xs[8] = {x0.x, x0.y, x0.z, x0.w, x1.x, x1.y, x1.z, x1.w};
        #pragma unroll
        for (int mi = 0; mi < 8; mi++) {
            ull d = fdup(xs[mi]);
            acc[mi][0] = ffma2(d, wA.x, acc[mi][0]);
            acc[mi][1] = ffma2(d, wA.y, acc[mi][1]);
            acc[mi][2] = ffma2(d, wB.x, acc[mi][2]);
            acc[mi][3] = ffma2(d, wB.y, acc[mi][3]);
        }
    }

    // ---- epilogue: bias + ReLU + zero-skip segment atomicMax ----
    float bj[8];
    #pragma unroll
    for (int ji = 0; ji < 8; ji++) bj[ji] = sb2[jb * 8 + ji];

    #pragma unroll
    for (int mi = 0; mi < 8; mi++) {
        int m = mb * 8 + mi;
        bool valid = (tile + m) < n;
        unsigned* ob = out + (size_t)sseg[m] * ED + jb * 8;
        #pragma unroll
        for (int jp = 0; jp < 4; jp++) {
            float a, b;
            funpack(acc[mi][jp], a, b);
            // ReLU outputs >= 0: uint bits order-preserving; init 0u == 0.0f.
            unsigned u0 = __float_as_uint(fmaxf(a + bj[jp * 2 + 0], 0.f));
            unsigned u1 = __float_as_uint(fmaxf(b + bj[jp * 2 + 1], 0.f));
            if (valid && u0) atomicMax(ob + jp * 2 + 0, u0);
            if (valid && u1) atomicMax(ob + jp * 2 + 1, u1);
        }
    }
}

extern "C" void kernel_launch(void* const* d_in, const int* in_sizes, int n_in,
                              void* d_out, int out_size)
{
    const float* X   = (const float*)d_in[0];
    const int*   seg = (const int*)  d_in[1];
    const float* W1  = (const float*)d_in[2];
    const float* b1  = (const float*)d_in[3];
    const float* W2  = (const float*)d_in[4];
    const float* b2  = (const float*)d_in[5];
    float* out = (float*)d_out;

    int n = in_sizes[1];   // number of points

    init_out_kernel<<<(out_size + 255) / 256, 256>>>(out, out_size);
    int tiles = (n + MT - 1) / MT;
    fused_mlp_segmax<<<tiles, 256>>>(X, seg, W1, b1, W2, b2, (unsigned*)out, n);
}

// round 4
// speedup vs baseline: 1.4516x; 1.0528x over previous
#include <cuda_runtime.h>
#include <cstddef>

#define FD 32
#define HD 64
#define ED 128
#define MT 128   // points per CTA tile

#define N_MAX    1600000
#define NSEG_MAX 65536

typedef unsigned long long ull;

__device__ int g_count[NSEG_MAX];
__device__ int g_cursor[NSEG_MAX];
__device__ int g_sorted[N_MAX];

__device__ __forceinline__ ull ffma2(ull a, ull b, ull c) {
    ull d;
    asm("fma.rn.f32x2 %0, %1, %2, %3;" : "=l"(d) : "l"(a), "l"(b), "l"(c));
    return d;
}
__device__ __forceinline__ ull fdup(float x) {
    ull d;
    asm("mov.b64 %0, {%1, %1};" : "=l"(d) : "f"(x));
    return d;
}
__device__ __forceinline__ void funpack(ull a, float& lo, float& hi) {
    asm("mov.b64 {%0, %1}, %2;" : "=f"(lo), "=f"(hi) : "l"(a));
}

// ---------------- sort pipeline ----------------

__global__ void zero_and_init(float* __restrict__ out, int out_n, int nseg) {
    int i = blockIdx.x * blockDim.x + threadIdx.x;
    if (i < out_n) out[i] = 0.0f;          // 0-init == isfinite guard for ReLU>=0 maxima
    if (i < nseg) g_count[i] = 0;
}

__global__ void hist_kernel(const int* __restrict__ seg, int n) {
    int i = blockIdx.x * blockDim.x + threadIdx.x;
    if (i < n) atomicAdd(&g_count[seg[i]], 1);
}

// Single-CTA chunked exclusive scan: g_cursor[s] = sum(g_count[<s]).
__global__ __launch_bounds__(1024) void scan_kernel(int nseg) {
    __shared__ int ssum[1024];
    int t = threadIdx.x;
    int C = (nseg + 1023) >> 10;
    int lo = t * C, hi = min(lo + C, nseg);
    int s = 0;
    for (int i = lo; i < hi; i++) s += g_count[i];
    ssum[t] = s;
    __syncthreads();
    for (int d = 1; d < 1024; d <<= 1) {
        int o = (t >= d) ? ssum[t - d] : 0;
        __syncthreads();
        ssum[t] += o;
        __syncthreads();
    }
    int pre = ssum[t] - s;   // exclusive prefix of this thread's chunk
    for (int i = lo; i < hi; i++) {
        int c = g_count[i];
        g_cursor[i] = pre;
        pre += c;
    }
}

__global__ void scatter_kernel(const int* __restrict__ seg, int n) {
    int i = blockIdx.x * blockDim.x + threadIdx.x;
    if (i < n) {
        int pos = atomicAdd(&g_cursor[seg[i]], 1);
        g_sorted[pos] = i;
    }
}

// ---------------- fused MLP + run-max segment reduction ----------------
// 256 threads, one 128-sorted-point tile per CTA.
// jb = t%16 (j-blocks), mb = t/16 (8 consecutive sorted points each).
__global__ __launch_bounds__(256, 2) void fused_mlp_segmax(
    const float* __restrict__ X,        // [N, 32]
    const int*   __restrict__ seg,      // [N]
    const float* __restrict__ W1,       // [32, 64]
    const float* __restrict__ b1,       // [64]
    const float* __restrict__ W2,       // [64, 128]
    const float* __restrict__ b2,       // [128]
    unsigned*    __restrict__ out,      // [NSEG, 128] as uint bits
    int n)
{
    __shared__ float sW1[FD * HD];      // [k][j], 8 KB
    __shared__ float sHX[HD * MT];      // H rows [j][m], 32 KB; X aliased rows 0..31
    __shared__ float sb1[HD];
    __shared__ float sb2[ED];
    __shared__ int   sseg[MT];

    int t = threadIdx.x;
    int tile = blockIdx.x * MT;

    // ---- stage W1, biases, sorted segment ids ----
    {
        const float4* W1g4 = reinterpret_cast<const float4*>(W1);
        float4* sW14 = reinterpret_cast<float4*>(sW1);
        sW14[t]       = __ldg(W1g4 + t);
        sW14[t + 256] = __ldg(W1g4 + t + 256);
    }
    if (t < HD) sb1[t] = b1[t];
    if (t < ED) sb2[t] = b2[t];
    if (t < MT) {
        int p = g_sorted[min(tile + t, n - 1)];
        sseg[t] = __ldg(seg + p);
    }

    // ---- gather X rows (sorted order) transposed into sHX[k][m] ----
    {
        int m  = t >> 1;
        int kh = (t & 1) * 16;
        int p  = g_sorted[min(tile + m, n - 1)];
        const float4* xr = reinterpret_cast<const float4*>(X + (size_t)p * FD) + (kh >> 2);
        #pragma unroll
        for (int i = 0; i < 4; i++) {
            float4 v = __ldg(xr + i);
            int k = kh + 4 * i;
            sHX[(k + 0) * MT + m] = v.x;
            sHX[(k + 1) * MT + m] = v.y;
            sHX[(k + 2) * MT + m] = v.z;
            sHX[(k + 3) * MT + m] = v.w;
        }
    }
    __syncthreads();

    int jb = t & 15;
    int mb = t >> 4;

    // ================= GEMM1: H = relu(X @ W1 + b1) =================
    ull acc1[8][2];
    #pragma unroll
    for (int mi = 0; mi < 8; mi++) { acc1[mi][0] = 0ull; acc1[mi][1] = 0ull; }

    #pragma unroll
    for (int k = 0; k < FD; k++) {
        ulonglong2 w = *reinterpret_cast<const ulonglong2*>(sW1 + k * HD + jb * 4);
        const float4* xr = reinterpret_cast<const float4*>(sHX + k * MT + mb * 8);
        float4 x0 = xr[0], x1 = xr[1];
        float xs[8] = {x0.x, x0.y, x0.z, x0.w, x1.x, x1.y, x1.z, x1.w};
        #pragma unroll
        for (int mi = 0; mi < 8; mi++) {
            ull d = fdup(xs[mi]);
            acc1[mi][0] = ffma2(d, w.x, acc1[mi][0]);
            acc1[mi][1] = ffma2(d, w.y, acc1[mi][1]);
        }
    }

    float h[8][4];
    {
        float bb0 = sb1[jb * 4 + 0], bb1 = sb1[jb * 4 + 1];
        float bb2v = sb1[jb * 4 + 2], bb3 = sb1[jb * 4 + 3];
        #pragma unroll
        for (int mi = 0; mi < 8; mi++) {
            float a, b;
            funpack(acc1[mi][0], a, b);
            h[mi][0] = fmaxf(a + bb0, 0.f);
            h[mi][1] = fmaxf(b + bb1, 0.f);
            funpack(acc1[mi][1], a, b);
            h[mi][2] = fmaxf(a + bb2v, 0.f);
            h[mi][3] = fmaxf(b + bb3, 0.f);
        }
    }
    __syncthreads();   // X reads done before H overwrites

    #pragma unroll
    for (int ji = 0; ji < 4; ji++) {
        int j = jb * 4 + ji;
        *reinterpret_cast<float4*>(sHX + j * MT + mb * 8) =
            make_float4(h[0][ji], h[1][ji], h[2][ji], h[3][ji]);
        *reinterpret_cast<float4*>(sHX + j * MT + mb * 8 + 4) =
            make_float4(h[4][ji], h[5][ji], h[6][ji], h[7][ji]);
    }
    __syncthreads();

    // ================= GEMM2: O = relu(H @ W2 + b2) =================
    ull acc[8][4];
    #pragma unroll
    for (int mi = 0; mi < 8; mi++)
        #pragma unroll
        for (int jp = 0; jp < 4; jp++) acc[mi][jp] = 0ull;

    const ulonglong2* W2g = reinterpret_cast<const ulonglong2*>(W2);
    #pragma unroll 8
    for (int k = 0; k < HD; k++) {
        ulonglong2 wA = __ldg(W2g + (size_t)k * (ED / 4) + jb * 2);
        ulonglong2 wB = __ldg(W2g + (size_t)k * (ED / 4) + jb * 2 + 1);
        const float4* xr = reinterpret_cast<const float4*>(sHX + k * MT + mb * 8);
        float4 x0 = xr[0], x1 = xr[1];
        float xs[8] = {x0.x, x0.y, x0.z, x0.w, x1.x, x1.y, x1.z, x1.w};
        #pragma unroll
        for (int mi = 0; mi < 8; mi++) {
            ull d = fdup(xs[mi]);
            acc[mi][0] = ffma2(d, wA.x, acc[mi][0]);
            acc[mi][1] = ffma2(d, wA.y, acc[mi][1]);
            acc[mi][2] = ffma2(d, wB.x, acc[mi][2]);
            acc[mi][3] = ffma2(d, wB.y, acc[mi][3]);
        }
    }

    // ---- epilogue: bias + ReLU + run-length segment max ----
    float bj[8];
    #pragma unroll
    for (int ji = 0; ji < 8; ji++) bj[ji] = sb2[jb * 8 + ji];

    int cur = -1;
    float rm[8];
    #pragma unroll
    for (int ji = 0; ji < 8; ji++) rm[ji] = 0.f;

    #pragma unroll
    for (int mi = 0; mi < 8; mi++) {
        int m = mb * 8 + mi;
        int s = ((tile + m) < n) ? sseg[m] : -1;

        float o[8];
        #pragma unroll
        for (int jp = 0; jp < 4; jp++) {
            float a, b;
            funpack(acc[mi][jp], a, b);
            o[2 * jp + 0] = fmaxf(a + bj[2 * jp + 0], 0.f);
            o[2 * jp + 1] = fmaxf(b + bj[2 * jp + 1], 0.f);
        }

        if (s != cur) {
            if (cur >= 0) {
                unsigned* ob = out + (size_t)cur * ED + jb * 8;
                #pragma unroll
                for (int ji = 0; ji < 8; ji++) {
                    unsigned u = __float_as_uint(rm[ji]);   // >=0: bit order == fp order
                    if (u) atomicMax(ob + ji, u);
                }
            }
            cur = s;
            #pragma unroll
            for (int ji = 0; ji < 8; ji++) rm[ji] = o[ji];
        } else {
            #pragma unroll
            for (int ji = 0; ji < 8; ji++) rm[ji] = fmaxf(rm[ji], o[ji]);
        }
    }
    if (cur >= 0) {
        unsigned* ob = out + (size_t)cur * ED + jb * 8;
        #pragma unroll
        for (int ji = 0; ji < 8; ji++) {
            unsigned u = __float_as_uint(rm[ji]);
            if (u) atomicMax(ob + ji, u);
        }
    }
}

extern "C" void kernel_launch(void* const* d_in, const int* in_sizes, int n_in,
                              void* d_out, int out_size)
{
    const float* X   = (const float*)d_in[0];
    const int*   seg = (const int*)  d_in[1];
    const float* W1  = (const float*)d_in[2];
    const float* b1  = (const float*)d_in[3];
    const float* W2  = (const float*)d_in[4];
    const float* b2  = (const float*)d_in[5];
    float* out = (float*)d_out;

    int n = in_sizes[1];               // number of points
    int nseg = out_size / ED;          // number of superpoints

    int initN = max(out_size, nseg);
    zero_and_init<<<(initN + 255) / 256, 256>>>(out, out_size, nseg);
    hist_kernel<<<(n + 255) / 256, 256>>>(seg, n);
    scan_kernel<<<1, 1024>>>(nseg);
    scatter_kernel<<<(n + 255) / 256, 256>>>(seg, n);

    int tiles = (n + MT - 1) / MT;
    fused_mlp_segmax<<<tiles, 256>>>(X, seg, W1, b1, W2, b2, (unsigned*)out, n);
}

// round 6
// speedup vs baseline: 1.7631x; 1.2146x over previous
#include <cuda_runtime.h>
#include <cuda_bf16.h>
#include <cstdint>
#include <cstddef>

#define FD 32
#define HD 64
#define ED 128
#define MT 128
#define TPC 4

#define N_MAX    1600000
#define NSEG_MAX 65536

__device__ int g_count[NSEG_MAX];
__device__ int g_cursor[NSEG_MAX];
__device__ int g_sorted[N_MAX];

// ---------------- smem layout (bytes) ----------------
// bf16 tiles, padded row strides for conflict-free ldmatrix:
//   X  : [128 m][k<32]  stride 80B  (40 bf16)
//   H  : [128 m][k<64]  stride 144B (72 bf16)
//   B1 : [64 n][k<32]   stride 80B   (W1^T)
//   B2 : [128 n][k<64]  stride 144B  (W2^T)
#define XS   80
#define HS   144
#define B1S  80
#define OFF_XHI  0
#define OFF_XLO  10240
#define OFF_HHI  20480
#define OFF_HLO  38912
#define OFF_B1HI 57344
#define OFF_B1LO 62464
#define OFF_B2HI 67584
#define OFF_B2LO 86016
#define OFF_SB1  104448
#define OFF_SB2  104704
#define OFF_SSEG 105216
#define SMEM_TOTAL 105728
#define OFF_O    0          // O staging [128][33] f32 = 16896B, aliases dead X region
#define O_PITCH  33

__device__ __forceinline__ uint32_t smem_u32_of(const void* p) {
    uint32_t a;
    asm("{ .reg .u64 t; cvta.to.shared.u64 t, %1; cvt.u32.u64 %0, t; }" : "=r"(a) : "l"(p));
    return a;
}
__device__ __forceinline__ void ldsm4(uint32_t& r0, uint32_t& r1, uint32_t& r2, uint32_t& r3, uint32_t a) {
    asm volatile("ldmatrix.sync.aligned.m8n8.x4.shared.b16 {%0,%1,%2,%3}, [%4];"
                 : "=r"(r0), "=r"(r1), "=r"(r2), "=r"(r3) : "r"(a));
}
__device__ __forceinline__ void mma16816(float* c, const uint32_t* a, uint32_t b0, uint32_t b1) {
    asm volatile("mma.sync.aligned.m16n8k16.row.col.f32.bf16.bf16.f32 "
                 "{%0,%1,%2,%3}, {%4,%5,%6,%7}, {%8,%9}, {%0,%1,%2,%3};"
                 : "+f"(c[0]), "+f"(c[1]), "+f"(c[2]), "+f"(c[3])
                 : "r"(a[0]), "r"(a[1]), "r"(a[2]), "r"(a[3]), "r"(b0), "r"(b1));
}
__device__ __forceinline__ void sts128(uint32_t a, uint32_t x, uint32_t y, uint32_t z, uint32_t w) {
    asm volatile("st.shared.v4.b32 [%0], {%1,%2,%3,%4};" :: "r"(a), "r"(x), "r"(y), "r"(z), "r"(w) : "memory");
}
__device__ __forceinline__ void split2(float v0, float v1, uint32_t& hi, uint32_t& lo) {
    __nv_bfloat16 h0 = __float2bfloat16_rn(v0);
    __nv_bfloat16 h1 = __float2bfloat16_rn(v1);
    __nv_bfloat16 l0 = __float2bfloat16_rn(v0 - __bfloat162float(h0));
    __nv_bfloat16 l1 = __float2bfloat16_rn(v1 - __bfloat162float(h1));
    __nv_bfloat162 hp = __halves2bfloat162(h0, h1);
    __nv_bfloat162 lp = __halves2bfloat162(l0, l1);
    hi = *reinterpret_cast<uint32_t*>(&hp);
    lo = *reinterpret_cast<uint32_t*>(&lp);
}
__device__ __forceinline__ void split1(float v, __nv_bfloat16& h, __nv_bfloat16& l) {
    h = __float2bfloat16_rn(v);
    l = __float2bfloat16_rn(v - __bfloat162float(h));
}

// ---------------- sort pipeline ----------------

__global__ void zero_and_init(float* __restrict__ out, int out_n, int nseg) {
    int i = blockIdx.x * blockDim.x + threadIdx.x;
    if (i < out_n) out[i] = 0.0f;          // 0-init == isfinite guard for ReLU>=0 maxima
    if (i < nseg) g_count[i] = 0;
}
__global__ void hist_kernel(const int* __restrict__ seg, int n) {
    int i = blockIdx.x * blockDim.x + threadIdx.x;
    if (i < n) atomicAdd(&g_count[seg[i]], 1);
}
__global__ __launch_bounds__(1024) void scan_kernel(int nseg) {
    __shared__ int ssum[1024];
    int t = threadIdx.x;
    int C = (nseg + 1023) >> 10;
    int lo = t * C, hi = min(lo + C, nseg);
    int s = 0;
    for (int i = lo; i < hi; i++) s += g_count[i];
    ssum[t] = s;
    __syncthreads();
    for (int d = 1; d < 1024; d <<= 1) {
        int o = (t >= d) ? ssum[t - d] : 0;
        __syncthreads();
        ssum[t] += o;
        __syncthreads();
    }
    int pre = ssum[t] - s;
    for (int i = lo; i < hi; i++) { int c = g_count[i]; g_cursor[i] = pre; pre += c; }
}
__global__ void scatter_kernel(const int* __restrict__ seg, int n) {
    int i = blockIdx.x * blockDim.x + threadIdx.x;
    if (i < n) { int pos = atomicAdd(&g_cursor[seg[i]], 1); g_sorted[pos] = i; }
}

// ---------------- tensor-core (warp MMA) fused MLP + segment max ----------------

__global__ __launch_bounds__(256, 2) void fused_mlp_segmax_mma(
    const float* __restrict__ X, const int* __restrict__ seg,
    const float* __restrict__ W1, const float* __restrict__ b1,
    const float* __restrict__ W2, const float* __restrict__ b2,
    unsigned* __restrict__ out, int n)
{
    extern __shared__ char smem[];
    const uint32_t su = smem_u32_of(smem);
    int t = threadIdx.x;
    int wid = t >> 5, lane = t & 31;
    int g = lane >> 2, tig = lane & 3;           // accum fragment coords
    int m0 = wid * 16;                            // this warp's 16 rows in the tile

    float* sb1 = (float*)(smem + OFF_SB1);
    float* sb2 = (float*)(smem + OFF_SB2);
    int*   ssg = (int*)(smem + OFF_SSEG);

    // ---- stage weights (once per CTA): bf16 hi/lo transposed [n][k] ----
    #pragma unroll
    for (int i = 0; i < 8; i++) {                 // B1: 64n x 32k
        int e = i * 256 + t, nn = e >> 5, k = e & 31;
        __nv_bfloat16 h, l;
        split1(W1[k * HD + nn], h, l);
        *(__nv_bfloat16*)(smem + OFF_B1HI + nn * B1S + k * 2) = h;
        *(__nv_bfloat16*)(smem + OFF_B1LO + nn * B1S + k * 2) = l;
    }
    #pragma unroll
    for (int i = 0; i < 32; i++) {                // B2: 128n x 64k
        int e = i * 256 + t, nn = e >> 6, k = e & 63;
        __nv_bfloat16 h, l;
        split1(W2[k * ED + nn], h, l);
        *(__nv_bfloat16*)(smem + OFF_B2HI + nn * HS + k * 2) = h;
        *(__nv_bfloat16*)(smem + OFF_B2LO + nn * HS + k * 2) = l;
    }
    if (t < HD) sb1[t] = b1[t];
    if (t < ED) sb2[t] = b2[t];
    __syncthreads();

    // lane-dependent ldmatrix base components
    int a_row = lane & 15;                        // A frag row within 16
    int a_koff = (lane >> 4) * 16;                // A frag k byte offset (8 elems)
    int b_nrow = (lane & 7) + ((lane >> 4) << 3); // B frag row within 16 (2 n-tiles)
    int b_koff = ((lane >> 3) & 1) * 16;          // B frag k byte offset

    int tiles_total = (n + MT - 1) >> 7;

    for (int it = 0; it < TPC; it++) {
        int tile = blockIdx.x * TPC + it;
        if (tile >= tiles_total) break;
        int base = tile << 7;

        // ---- stage sorted seg ids + X tile (bf16 hi/lo) ----
        if (t < MT) ssg[t] = seg[g_sorted[min(base + t, n - 1)]];
        {
            int m = t >> 1, half = t & 1;         // 2 threads per row, 16 k each
            int p = g_sorted[min(base + m, n - 1)];
            const float4* xr = reinterpret_cast<const float4*>(X + (size_t)p * FD) + half * 4;
            uint32_t hw[8], lw[8];
            #pragma unroll
            for (int i = 0; i < 4; i++) {
                float4 v = __ldg(xr + i);
                split2(v.x, v.y, hw[2 * i], lw[2 * i]);
                split2(v.z, v.w, hw[2 * i + 1], lw[2 * i + 1]);
            }
            uint32_t o0 = (uint32_t)(m * XS + half * 32);
            sts128(su + OFF_XHI + o0,      hw[0], hw[1], hw[2], hw[3]);
            sts128(su + OFF_XHI + o0 + 16, hw[4], hw[5], hw[6], hw[7]);
            sts128(su + OFF_XLO + o0,      lw[0], lw[1], lw[2], lw[3]);
            sts128(su + OFF_XLO + o0 + 16, lw[4], lw[5], lw[6], lw[7]);
        }
        __syncwarp();   // warp w staged exactly rows 16w..16w+15, which it consumes

        // ================ GEMM1: H = relu(X @ W1 + b1), 16m x 64n ================
        float acc1[8][4];
        #pragma unroll
        for (int nt = 0; nt < 8; nt++)
            #pragma unroll
            for (int c = 0; c < 4; c++) acc1[nt][c] = 0.f;

        #pragma unroll
        for (int ks = 0; ks < 2; ks++) {
            uint32_t ah[4], al[4];
            uint32_t aaddr = su + (uint32_t)((m0 + a_row) * XS + ks * 32 + a_koff);
            ldsm4(ah[0], ah[1], ah[2], ah[3], aaddr + OFF_XHI);
            ldsm4(al[0], al[1], al[2], al[3], aaddr + OFF_XLO);
            #pragma unroll
            for (int ntp = 0; ntp < 4; ntp++) {
                uint32_t bh[4], bl[4];
                uint32_t baddr = su + (uint32_t)((16 * ntp + b_nrow) * B1S + ks * 32 + b_koff);
                ldsm4(bh[0], bh[1], bh[2], bh[3], baddr + OFF_B1HI);
                ldsm4(bl[0], bl[1], bl[2], bl[3], baddr + OFF_B1LO);
                mma16816(acc1[2 * ntp],     ah, bh[0], bh[1]);
                mma16816(acc1[2 * ntp + 1], ah, bh[2], bh[3]);
                mma16816(acc1[2 * ntp],     ah, bl[0], bl[1]);
                mma16816(acc1[2 * ntp + 1], ah, bl[2], bl[3]);
                mma16816(acc1[2 * ntp],     al, bh[0], bh[1]);
                mma16816(acc1[2 * ntp + 1], al, bh[2], bh[3]);
            }
        }

        // ---- H = relu(+b1) -> bf16 hi/lo into smem (own rows only) ----
        #pragma unroll
        for (int nt = 0; nt < 8; nt++) {
            int j = 8 * nt + 2 * tig;
            float bb0 = sb1[j], bb1 = sb1[j + 1];
            uint32_t hi, lo;
            split2(fmaxf(acc1[nt][0] + bb0, 0.f), fmaxf(acc1[nt][1] + bb1, 0.f), hi, lo);
            uint32_t oA = (uint32_t)((m0 + g) * HS + j * 2);
            *(uint32_t*)(smem + OFF_HHI + oA) = hi;
            *(uint32_t*)(smem + OFF_HLO + oA) = lo;
            split2(fmaxf(acc1[nt][2] + bb0, 0.f), fmaxf(acc1[nt][3] + bb1, 0.f), hi, lo);
            uint32_t oB = (uint32_t)((m0 + g + 8) * HS + j * 2);
            *(uint32_t*)(smem + OFF_HHI + oB) = hi;
            *(uint32_t*)(smem + OFF_HLO + oB) = lo;
        }
        __syncwarp();

        // ================ GEMM2 (two 64-col halves) + epilogue ================
        #pragma unroll 1
        for (int nh = 0; nh < 2; nh++) {
            float acc[8][4];
            #pragma unroll
            for (int nt = 0; nt < 8; nt++)
                #pragma unroll
                for (int c = 0; c < 4; c++) acc[nt][c] = 0.f;

            #pragma unroll
            for (int ks = 0; ks < 4; ks++) {
                uint32_t ah[4], al[4];
                uint32_t aaddr = su + (uint32_t)((m0 + a_row) * HS + ks * 32 + a_koff);
                ldsm4(ah[0], ah[1], ah[2], ah[3], aaddr + OFF_HHI);
                ldsm4(al[0], al[1], al[2], al[3], aaddr + OFF_HLO);
                #pragma unroll
                for (int ntp = 0; ntp < 4; ntp++) {
                    int nrow = 64 * nh + 16 * ntp;
                    uint32_t bh[4], bl[4];
                    uint32_t baddr = su + (uint32_t)((nrow + b_nrow) * HS + ks * 32 + b_koff);
                    ldsm4(bh[0], bh[1], bh[2], bh[3], baddr + OFF_B2HI);
                    ldsm4(bl[0], bl[1], bl[2], bl[3], baddr + OFF_B2LO);
                    mma16816(acc[2 * ntp],     ah, bh[0], bh[1]);
                    mma16816(acc[2 * ntp + 1], ah, bh[2], bh[3]);
                    mma16816(acc[2 * ntp],     ah, bl[0], bl[1]);
                    mma16816(acc[2 * ntp + 1], ah, bl[2], bl[3]);
                    mma16816(acc[2 * ntp],     al, bh[0], bh[1]);
                    mma16816(acc[2 * ntp + 1], al, bh[2], bh[3]);
                }
            }

            // epilogue: 2 passes of 32 cols, O staged over dead X region
            #pragma unroll 1
            for (int p = 0; p < 2; p++) {
                float* O = (float*)(smem + OFF_O);
                #pragma unroll
                for (int q = 0; q < 4; q++) {
                    int nt = 4 * p + q;
                    int cl = 8 * q + 2 * tig;             // col within 32-col stage
                    int jg = 64 * nh + 32 * p + cl;
                    float bb0 = sb2[jg], bb1 = sb2[jg + 1];
                    float* rA = O + (m0 + g) * O_PITCH + cl;
                    rA[0] = fmaxf(acc[nt][0] + bb0, 0.f);
                    rA[1] = fmaxf(acc[nt][1] + bb1, 0.f);
                    float* rB = O + (m0 + g + 8) * O_PITCH + cl;
                    rB[0] = fmaxf(acc[nt][2] + bb0, 0.f);
                    rB[1] = fmaxf(acc[nt][3] + bb1, 0.f);
                }
                __syncthreads();
                {   // run-length segment max: thread = 1 col x 16 sorted points
                    int jgl = t & 31, mg = t >> 5;
                    int j = 64 * nh + 32 * p + jgl;
                    const float* ocol = (const float*)(smem + OFF_O) + jgl;
                    float rm = 0.f; int cs = -1;
                    #pragma unroll
                    for (int mi = 0; mi < 16; mi++) {
                        int m2 = mg * 16 + mi;
                        int s = ssg[m2];
                        float v = ocol[m2 * O_PITCH];
                        if (s != cs) {
                            if (cs >= 0) {
                                unsigned u = __float_as_uint(rm);  // >=0: bit order == fp order
                                if (u) atomicMax(out + (size_t)cs * ED + j, u);
                            }
                            cs = s; rm = v;
                        } else rm = fmaxf(rm, v);
                    }
                    if (cs >= 0) {
                        unsigned u = __float_as_uint(rm);
                        if (u) atomicMax(out + (size_t)cs * ED + j, u);
                    }
                }
                __syncthreads();
            }
        }
    }
}

extern "C" void kernel_launch(void* const* d_in, const int* in_sizes, int n_in,
                              void* d_out, int out_size)
{
    const float* X   = (const float*)d_in[0];
    const int*   seg = (const int*)  d_in[1];
    const float* W1  = (const float*)d_in[2];
    const float* b1  = (const float*)d_in[3];
    const float* W2  = (const float*)d_in[4];
    const float* b2  = (const float*)d_in[5];
    float* out = (float*)d_out;

    int n = in_sizes[1];
    int nseg = out_size / ED;

    cudaFuncSetAttribute(fused_mlp_segmax_mma,
                         cudaFuncAttributeMaxDynamicSharedMemorySize, SMEM_TOTAL);

    int initN = max(out_size, nseg);
    zero_and_init<<<(initN + 255) / 256, 256>>>(out, out_size, nseg);
    hist_kernel<<<(n + 255) / 256, 256>>>(seg, n);
    scan_kernel<<<1, 1024>>>(nseg);
    scatter_kernel<<<(n + 255) / 256, 256>>>(seg, n);

    int tiles = (n + MT - 1) / MT;
    int grid = (tiles + TPC - 1) / TPC;
    fused_mlp_segmax_mma<<<grid, 256, SMEM_TOTAL>>>(X, seg, W1, b1, W2, b2, (unsigned*)out, n);
}

// round 7
// speedup vs baseline: 2.1740x; 1.2331x over previous
#include <cuda_runtime.h>
#include <cuda_fp16.h>
#include <cstdint>
#include <cstddef>

#define FD 32
#define HD 64
#define ED 128
#define MT 128
#define TPC 4

#define N_MAX    1600000
#define NSEG_MAX 65536

__device__ int g_count[NSEG_MAX];
__device__ int g_cursor[NSEG_MAX];
__device__ int g_sorted[N_MAX];

// ---------------- smem layout (bytes) ----------------
// fp16 tiles, padded row strides for conflict-free ldmatrix:
//   Xhi/Xlo : [128 m][k<32]  stride 80B
//   Hhi/Hlo : [128 m][k<64]  stride 144B
//   B1      : [64 n][k<32]   stride 80B   (W1^T, fp16 single)
//   B2      : [128 n][k<64]  stride 144B  (W2^T, fp16 single)
//   O       : per-warp [16][33] f32 staging (dedicated, no aliasing)
#define XS   80
#define HS   144
#define B1S  80
#define OFF_XHI  0
#define OFF_XLO  10240
#define OFF_HHI  20480
#define OFF_HLO  38912
#define OFF_B1   57344
#define OFF_B2   62464
#define OFF_O    80896
#define OFF_SB1  97792
#define OFF_SB2  98048
#define OFF_SSEG 98560
#define SMEM_TOTAL 99072
#define O_PITCH  33

__device__ __forceinline__ uint32_t smem_u32_of(const void* p) {
    uint32_t a;
    asm("{ .reg .u64 t; cvta.to.shared.u64 t, %1; cvt.u32.u64 %0, t; }" : "=r"(a) : "l"(p));
    return a;
}
__device__ __forceinline__ void ldsm4(uint32_t& r0, uint32_t& r1, uint32_t& r2, uint32_t& r3, uint32_t a) {
    asm volatile("ldmatrix.sync.aligned.m8n8.x4.shared.b16 {%0,%1,%2,%3}, [%4];"
                 : "=r"(r0), "=r"(r1), "=r"(r2), "=r"(r3) : "r"(a));
}
__device__ __forceinline__ void mma16816(float* c, const uint32_t* a, uint32_t b0, uint32_t b1) {
    asm volatile("mma.sync.aligned.m16n8k16.row.col.f32.f16.f16.f32 "
                 "{%0,%1,%2,%3}, {%4,%5,%6,%7}, {%8,%9}, {%0,%1,%2,%3};"
                 : "+f"(c[0]), "+f"(c[1]), "+f"(c[2]), "+f"(c[3])
                 : "r"(a[0]), "r"(a[1]), "r"(a[2]), "r"(a[3]), "r"(b0), "r"(b1));
}
__device__ __forceinline__ void sts128(uint32_t a, uint32_t x, uint32_t y, uint32_t z, uint32_t w) {
    asm volatile("st.shared.v4.b32 [%0], {%1,%2,%3,%4};" :: "r"(a), "r"(x), "r"(y), "r"(z), "r"(w) : "memory");
}
// fp16 hi/lo split of a float pair, packed as half2 words
__device__ __forceinline__ void split2(float v0, float v1, uint32_t& hi, uint32_t& lo) {
    __half h0 = __float2half_rn(v0);
    __half h1 = __float2half_rn(v1);
    __half l0 = __float2half_rn(v0 - __half2float(h0));
    __half l1 = __float2half_rn(v1 - __half2float(h1));
    __half2 hp = __halves2half2(h0, h1);
    __half2 lp = __halves2half2(l0, l1);
    hi = *reinterpret_cast<uint32_t*>(&hp);
    lo = *reinterpret_cast<uint32_t*>(&lp);
}

// ---------------- sort pipeline ----------------

__global__ void zero_and_init(float* __restrict__ out, int out_n, int nseg) {
    int i = blockIdx.x * blockDim.x + threadIdx.x;
    if (i < out_n) out[i] = 0.0f;          // 0-init == isfinite guard for ReLU>=0 maxima
    if (i < nseg) g_count[i] = 0;
}
__global__ void hist_kernel(const int* __restrict__ seg, int n) {
    int i = blockIdx.x * blockDim.x + threadIdx.x;
    if (i < n) atomicAdd(&g_count[seg[i]], 1);
}
__global__ __launch_bounds__(1024) void scan_kernel(int nseg) {
    __shared__ int ssum[1024];
    int t = threadIdx.x;
    int C = (nseg + 1023) >> 10;
    int lo = t * C, hi = min(lo + C, nseg);
    int s = 0;
    for (int i = lo; i < hi; i++) s += g_count[i];
    ssum[t] = s;
    __syncthreads();
    for (int d = 1; d < 1024; d <<= 1) {
        int o = (t >= d) ? ssum[t - d] : 0;
        __syncthreads();
        ssum[t] += o;
        __syncthreads();
    }
    int pre = ssum[t] - s;
    for (int i = lo; i < hi; i++) { int c = g_count[i]; g_cursor[i] = pre; pre += c; }
}
__global__ void scatter_kernel(const int* __restrict__ seg, int n) {
    int i = blockIdx.x * blockDim.x + threadIdx.x;
    if (i < n) { int pos = atomicAdd(&g_cursor[seg[i]], 1); g_sorted[pos] = i; }
}

// ---------------- warp-MMA fused MLP + segment max (no block barriers in loop) ----------------

__global__ __launch_bounds__(256, 2) void fused_mlp_segmax_mma(
    const float* __restrict__ X, const int* __restrict__ seg,
    const float* __restrict__ W1, const float* __restrict__ b1,
    const float* __restrict__ W2, const float* __restrict__ b2,
    unsigned* __restrict__ out, int n)
{
    extern __shared__ char smem[];
    const uint32_t su = smem_u32_of(smem);
    int t = threadIdx.x;
    int wid = t >> 5, lane = t & 31;
    int g = lane >> 2, tig = lane & 3;
    int m0 = wid * 16;

    float* sb1 = (float*)(smem + OFF_SB1);
    float* sb2 = (float*)(smem + OFF_SB2);
    int*   ssg = (int*)(smem + OFF_SSEG);
    float* OW  = (float*)(smem + OFF_O) + wid * 16 * O_PITCH;   // per-warp staging

    // ---- stage fp16 weights (once per CTA), transposed [n][k] ----
    #pragma unroll
    for (int i = 0; i < 8; i++) {                 // B1: 64n x 32k
        int e = i * 256 + t, nn = e >> 5, k = e & 31;
        *(__half*)(smem + OFF_B1 + nn * B1S + k * 2) = __float2half_rn(W1[k * HD + nn]);
    }
    #pragma unroll
    for (int i = 0; i < 32; i++) {                // B2: 128n x 64k
        int e = i * 256 + t, nn = e >> 6, k = e & 63;
        *(__half*)(smem + OFF_B2 + nn * HS + k * 2) = __float2half_rn(W2[k * ED + nn]);
    }
    if (t < HD) sb1[t] = b1[t];
    if (t < ED) sb2[t] = b2[t];
    __syncthreads();   // the only block barrier

    int a_row = lane & 15;
    int a_koff = (lane >> 4) * 16;
    int b_nrow = (lane & 7) + ((lane >> 4) << 3);
    int b_koff = ((lane >> 3) & 1) * 16;

    int tiles_total = (n + MT - 1) >> 7;

    for (int it = 0; it < TPC; it++) {
        int tile = blockIdx.x * TPC + it;
        if (tile >= tiles_total) break;
        int base = tile << 7;

        // ---- warp-local staging: seg ids + X tile (fp16 hi/lo) ----
        if (lane < 16)
            ssg[m0 + lane] = seg[g_sorted[min(base + m0 + lane, n - 1)]];
        {
            int m = t >> 1, half = t & 1;         // rows m0..m0+15 staged by own warp
            int p = g_sorted[min(base + m, n - 1)];
            const float4* xr = reinterpret_cast<const float4*>(X + (size_t)p * FD) + half * 4;
            uint32_t hw[8], lw[8];
            #pragma unroll
            for (int i = 0; i < 4; i++) {
                float4 v = __ldg(xr + i);
                split2(v.x, v.y, hw[2 * i], lw[2 * i]);
                split2(v.z, v.w, hw[2 * i + 1], lw[2 * i + 1]);
            }
            uint32_t o0 = (uint32_t)(m * XS + half * 32);
            sts128(su + OFF_XHI + o0,      hw[0], hw[1], hw[2], hw[3]);
            sts128(su + OFF_XHI + o0 + 16, hw[4], hw[5], hw[6], hw[7]);
            sts128(su + OFF_XLO + o0,      lw[0], lw[1], lw[2], lw[3]);
            sts128(su + OFF_XLO + o0 + 16, lw[4], lw[5], lw[6], lw[7]);
        }
        __syncwarp();

        // ================ GEMM1: H = relu(X @ W1 + b1), 16m x 64n ================
        float acc1[8][4];
        #pragma unroll
        for (int nt = 0; nt < 8; nt++)
            #pragma unroll
            for (int c = 0; c < 4; c++) acc1[nt][c] = 0.f;

        #pragma unroll
        for (int ks = 0; ks < 2; ks++) {
            uint32_t ah[4], al[4];
            uint32_t aaddr = su + (uint32_t)((m0 + a_row) * XS + ks * 32 + a_koff);
            ldsm4(ah[0], ah[1], ah[2], ah[3], aaddr + OFF_XHI);
            ldsm4(al[0], al[1], al[2], al[3], aaddr + OFF_XLO);
            #pragma unroll
            for (int ntp = 0; ntp < 4; ntp++) {
                uint32_t bh[4];
                uint32_t baddr = su + (uint32_t)((16 * ntp + b_nrow) * B1S + ks * 32 + b_koff);
                ldsm4(bh[0], bh[1], bh[2], bh[3], baddr + OFF_B1);
                mma16816(acc1[2 * ntp],     ah, bh[0], bh[1]);
                mma16816(acc1[2 * ntp + 1], ah, bh[2], bh[3]);
                mma16816(acc1[2 * ntp],     al, bh[0], bh[1]);
                mma16816(acc1[2 * ntp + 1], al, bh[2], bh[3]);
            }
        }

        // ---- H = relu(+b1) -> fp16 hi/lo into smem (own rows only) ----
        #pragma unroll
        for (int nt = 0; nt < 8; nt++) {
            int j = 8 * nt + 2 * tig;
            float bb0 = sb1[j], bb1 = sb1[j + 1];
            uint32_t hi, lo;
            split2(fmaxf(acc1[nt][0] + bb0, 0.f), fmaxf(acc1[nt][1] + bb1, 0.f), hi, lo);
            uint32_t oA = (uint32_t)((m0 + g) * HS + j * 2);
            *(uint32_t*)(smem + OFF_HHI + oA) = hi;
            *(uint32_t*)(smem + OFF_HLO + oA) = lo;
            split2(fmaxf(acc1[nt][2] + bb0, 0.f), fmaxf(acc1[nt][3] + bb1, 0.f), hi, lo);
            uint32_t oB = (uint32_t)((m0 + g + 8) * HS + j * 2);
            *(uint32_t*)(smem + OFF_HHI + oB) = hi;
            *(uint32_t*)(smem + OFF_HLO + oB) = lo;
        }
        __syncwarp();

        // ---- hoist GEMM2 A-fragments (reused for both n-halves) ----
        uint32_t Ah[4][4], Al[4][4];
        #pragma unroll
        for (int ks = 0; ks < 4; ks++) {
            uint32_t aaddr = su + (uint32_t)((m0 + a_row) * HS + ks * 32 + a_koff);
            ldsm4(Ah[ks][0], Ah[ks][1], Ah[ks][2], Ah[ks][3], aaddr + OFF_HHI);
            ldsm4(Al[ks][0], Al[ks][1], Al[ks][2], Al[ks][3], aaddr + OFF_HLO);
        }

        // ================ GEMM2 (two 64-col halves) + per-warp epilogue ================
        #pragma unroll 1
        for (int nh = 0; nh < 2; nh++) {
            float acc[8][4];
            #pragma unroll
            for (int nt = 0; nt < 8; nt++)
                #pragma unroll
                for (int c = 0; c < 4; c++) acc[nt][c] = 0.f;

            #pragma unroll
            for (int ks = 0; ks < 4; ks++) {
                #pragma unroll
                for (int ntp = 0; ntp < 4; ntp++) {
                    int nrow = 64 * nh + 16 * ntp;
                    uint32_t bh[4];
                    uint32_t baddr = su + (uint32_t)((nrow + b_nrow) * HS + ks * 32 + b_koff);
                    ldsm4(bh[0], bh[1], bh[2], bh[3], baddr + OFF_B2);
                    mma16816(acc[2 * ntp],     Ah[ks], bh[0], bh[1]);
                    mma16816(acc[2 * ntp + 1], Ah[ks], bh[2], bh[3]);
                    mma16816(acc[2 * ntp],     Al[ks], bh[0], bh[1]);
                    mma16816(acc[2 * ntp + 1], Al[ks], bh[2], bh[3]);
                }
            }

            // per-warp epilogue: 2 passes of 32 cols through warp-private O staging
            #pragma unroll 1
            for (int p = 0; p < 2; p++) {
                __syncwarp();      // previous pass reads complete before overwrite
                #pragma unroll
                for (int q = 0; q < 4; q++) {
                    int nt = 4 * p + q;
                    int cl = 8 * q + 2 * tig;
                    int jg = 64 * nh + 32 * p + cl;
                    float bb0 = sb2[jg], bb1 = sb2[jg + 1];
                    float* rA = OW + g * O_PITCH + cl;
                    rA[0] = fmaxf(acc[nt][0] + bb0, 0.f);
                    rA[1] = fmaxf(acc[nt][1] + bb1, 0.f);
                    float* rB = OW + (g + 8) * O_PITCH + cl;
                    rB[0] = fmaxf(acc[nt][2] + bb0, 0.f);
                    rB[1] = fmaxf(acc[nt][3] + bb1, 0.f);
                }
                __syncwarp();
                {   // run-length segment max: lane = 1 col x this warp's 16 sorted rows
                    int j = 64 * nh + 32 * p + lane;
                    const float* ocol = OW + lane;
                    float rm = 0.f; int cs = -1;
                    #pragma unroll
                    for (int mi = 0; mi < 16; mi++) {
                        int s = ssg[m0 + mi];
                        float v = ocol[mi * O_PITCH];
                        if (s != cs) {
                            if (cs >= 0) {
                                unsigned u = __float_as_uint(rm);  // >=0: bit order == fp order
                                if (u) atomicMax(out + (size_t)cs * ED + j, u);
                            }
                            cs = s; rm = v;
                        } else rm = fmaxf(rm, v);
                    }
                    if (cs >= 0) {
                        unsigned u = __float_as_uint(rm);
                        if (u) atomicMax(out + (size_t)cs * ED + j, u);
                    }
                }
            }
        }
        __syncwarp();   // O/X/H regions quiesced before next tile restage
    }
}

extern "C" void kernel_launch(void* const* d_in, const int* in_sizes, int n_in,
                              void* d_out, int out_size)
{
    const float* X   = (const float*)d_in[0];
    const int*   seg = (const int*)  d_in[1];
    const float* W1  = (const float*)d_in[2];
    const float* b1  = (const float*)d_in[3];
    const float* W2  = (const float*)d_in[4];
    const float* b2  = (const float*)d_in[5];
    float* out = (float*)d_out;

    int n = in_sizes[1];
    int nseg = out_size / ED;

    cudaFuncSetAttribute(fused_mlp_segmax_mma,
                         cudaFuncAttributeMaxDynamicSharedMemorySize, SMEM_TOTAL);

    int initN = max(out_size, nseg);
    zero_and_init<<<(initN + 255) / 256, 256>>>(out, out_size, nseg);
    hist_kernel<<<(n + 255) / 256, 256>>>(seg, n);
    scan_kernel<<<1, 1024>>>(nseg);
    scatter_kernel<<<(n + 255) / 256, 256>>>(seg, n);

    int tiles = (n + MT - 1) / MT;
    int grid = (tiles + TPC - 1) / TPC;
    fused_mlp_segmax_mma<<<grid, 256, SMEM_TOTAL>>>(X, seg, W1, b1, W2, b2, (unsigned*)out, n);
}

// round 8
// speedup vs baseline: 2.7302x; 1.2558x over previous
#include <cuda_runtime.h>
#include <cuda_fp16.h>
#include <cstdint>
#include <cstddef>

#define FD 32
#define HD 64
#define ED 128
#define MT 128
#define TPC 4

#define N_MAX    1600000
#define NSEG_MAX 65536

__device__ int g_count[NSEG_MAX];
__device__ int g_cursor[NSEG_MAX];
__device__ int g_sorted[N_MAX];

// ---------------- smem layout (bytes) ----------------
//   Xhi/Xlo : [128 m][k<32]  stride 80B   (fp16 hi/lo split of X)
//   Hhi     : [128 m][k<64]  stride 144B  (fp16 single)
//   B1      : [64 n][k<32]   stride 80B   (W1^T fp16)
//   B2      : [128 n][k<64]  stride 144B  (W2^T fp16)
//   O       : per-warp [16][33] f32 staging
#define XS   80
#define HS   144
#define B1S  80
#define OFF_XHI  0
#define OFF_XLO  10240
#define OFF_HHI  20480
#define OFF_B1   38912
#define OFF_B2   44032
#define OFF_O    62464
#define OFF_SB1  79360
#define OFF_SB2  79616
#define OFF_SSEG 80128
#define SMEM_TOTAL 80640
#define O_PITCH  33

__device__ __forceinline__ uint32_t smem_u32_of(const void* p) {
    uint32_t a;
    asm("{ .reg .u64 t; cvta.to.shared.u64 t, %1; cvt.u32.u64 %0, t; }" : "=r"(a) : "l"(p));
    return a;
}
__device__ __forceinline__ void ldsm4(uint32_t& r0, uint32_t& r1, uint32_t& r2, uint32_t& r3, uint32_t a) {
    asm volatile("ldmatrix.sync.aligned.m8n8.x4.shared.b16 {%0,%1,%2,%3}, [%4];"
                 : "=r"(r0), "=r"(r1), "=r"(r2), "=r"(r3) : "r"(a));
}
__device__ __forceinline__ void mma16816(float* c, const uint32_t* a, uint32_t b0, uint32_t b1) {
    asm volatile("mma.sync.aligned.m16n8k16.row.col.f32.f16.f16.f32 "
                 "{%0,%1,%2,%3}, {%4,%5,%6,%7}, {%8,%9}, {%0,%1,%2,%3};"
                 : "+f"(c[0]), "+f"(c[1]), "+f"(c[2]), "+f"(c[3])
                 : "r"(a[0]), "r"(a[1]), "r"(a[2]), "r"(a[3]), "r"(b0), "r"(b1));
}
__device__ __forceinline__ void sts128(uint32_t a, uint32_t x, uint32_t y, uint32_t z, uint32_t w) {
    asm volatile("st.shared.v4.b32 [%0], {%1,%2,%3,%4};" :: "r"(a), "r"(x), "r"(y), "r"(z), "r"(w) : "memory");
}
// fp16 hi/lo split of a float pair
__device__ __forceinline__ void split2(float v0, float v1, uint32_t& hi, uint32_t& lo) {
    __half h0 = __float2half_rn(v0);
    __half h1 = __float2half_rn(v1);
    __half l0 = __float2half_rn(v0 - __half2float(h0));
    __half l1 = __float2half_rn(v1 - __half2float(h1));
    __half2 hp = __halves2half2(h0, h1);
    __half2 lp = __halves2half2(l0, l1);
    hi = *reinterpret_cast<uint32_t*>(&hp);
    lo = *reinterpret_cast<uint32_t*>(&lp);
}
__device__ __forceinline__ uint32_t pack2(float v0, float v1) {
    __half2 h = __floats2half2_rn(v0, v1);
    return *reinterpret_cast<uint32_t*>(&h);
}

// ---------------- sort pipeline ----------------

__global__ void zero_and_init(float* __restrict__ out, int out_n, int nseg) {
    int i = blockIdx.x * blockDim.x + threadIdx.x;
    if (i < out_n) out[i] = 0.0f;          // 0-init == isfinite guard for ReLU>=0 maxima
    if (i < nseg) g_count[i] = 0;
}
__global__ void hist_kernel(const int* __restrict__ seg, int n) {
    int i = blockIdx.x * blockDim.x + threadIdx.x;
    if (i < n) atomicAdd(&g_count[seg[i]], 1);
}
__global__ __launch_bounds__(1024) void scan_kernel(int nseg) {
    __shared__ int ssum[1024];
    int t = threadIdx.x;
    int C = (nseg + 1023) >> 10;
    int lo = t * C, hi = min(lo + C, nseg);
    int s = 0;
    for (int i = lo; i < hi; i++) s += g_count[i];
    ssum[t] = s;
    __syncthreads();
    for (int d = 1; d < 1024; d <<= 1) {
        int o = (t >= d) ? ssum[t - d] : 0;
        __syncthreads();
        ssum[t] += o;
        __syncthreads();
    }
    int pre = ssum[t] - s;
    for (int i = lo; i < hi; i++) { int c = g_count[i]; g_cursor[i] = pre; pre += c; }
}
__global__ void scatter_kernel(const int* __restrict__ seg, int n) {
    int i = blockIdx.x * blockDim.x + threadIdx.x;
    if (i < n) { int pos = atomicAdd(&g_cursor[seg[i]], 1); g_sorted[pos] = i; }
}

// ---------------- warp-MMA fused MLP + segment max ----------------

__global__ __launch_bounds__(256, 2) void fused_mlp_segmax_mma(
    const float* __restrict__ X, const int* __restrict__ seg,
    const float* __restrict__ W1, const float* __restrict__ b1,
    const float* __restrict__ W2, const float* __restrict__ b2,
    unsigned* __restrict__ out, int n)
{
    extern __shared__ char smem[];
    const uint32_t su = smem_u32_of(smem);
    int t = threadIdx.x;
    int wid = t >> 5, lane = t & 31;
    int g = lane >> 2, tig = lane & 3;
    int m0 = wid * 16;

    float* sb1 = (float*)(smem + OFF_SB1);
    float* sb2 = (float*)(smem + OFF_SB2);
    int*   ssg = (int*)(smem + OFF_SSEG);
    float* OW  = (float*)(smem + OFF_O) + wid * 16 * O_PITCH;

    // ---- stage fp16 weights, COALESCED (lanes walk n, not k) ----
    #pragma unroll
    for (int i = 0; i < 8; i++) {                 // B1: 64n x 32k
        int e = i * 256 + t, nn = e & 63, k = e >> 6;
        *(__half*)(smem + OFF_B1 + nn * B1S + k * 2) = __float2half_rn(W1[k * HD + nn]);
    }
    #pragma unroll
    for (int i = 0; i < 32; i++) {                // B2: 128n x 64k
        int e = i * 256 + t, nn = e & 127, k = e >> 7;
        *(__half*)(smem + OFF_B2 + nn * HS + k * 2) = __float2half_rn(W2[k * ED + nn]);
    }
    if (t < HD) sb1[t] = b1[t];
    if (t < ED) sb2[t] = b2[t];
    __syncthreads();   // the only block barrier

    int a_row = lane & 15;
    int a_koff = (lane >> 4) * 16;
    int b_nrow = (lane & 7) + ((lane >> 4) << 3);
    int b_koff = ((lane >> 3) & 1) * 16;

    int tiles_total = (n + MT - 1) >> 7;

    for (int it = 0; it < TPC; it++) {
        int tile = blockIdx.x * TPC + it;
        if (tile >= tiles_total) break;
        int base = tile << 7;

        // ---- warp-local staging: seg ids + X tile (fp16 hi/lo) ----
        if (lane < 16)
            ssg[m0 + lane] = seg[g_sorted[min(base + m0 + lane, n - 1)]];
        {
            int m = t >> 1, half = t & 1;         // warp stages its own 16 rows
            int p = g_sorted[min(base + m, n - 1)];
            const float4* xr = reinterpret_cast<const float4*>(X + (size_t)p * FD) + half * 4;
            uint32_t hw[8], lw[8];
            #pragma unroll
            for (int i = 0; i < 4; i++) {
                float4 v = __ldg(xr + i);
                split2(v.x, v.y, hw[2 * i], lw[2 * i]);
                split2(v.z, v.w, hw[2 * i + 1], lw[2 * i + 1]);
            }
            uint32_t o0 = (uint32_t)(m * XS + half * 32);
            sts128(su + OFF_XHI + o0,      hw[0], hw[1], hw[2], hw[3]);
            sts128(su + OFF_XHI + o0 + 16, hw[4], hw[5], hw[6], hw[7]);
            sts128(su + OFF_XLO + o0,      lw[0], lw[1], lw[2], lw[3]);
            sts128(su + OFF_XLO + o0 + 16, lw[4], lw[5], lw[6], lw[7]);
        }
        __syncwarp();

        // ================ GEMM1: H = relu(X @ W1 + b1), 16m x 64n, A 2-term ================
        float acc1[8][4];
        #pragma unroll
        for (int nt = 0; nt < 8; nt++)
            #pragma unroll
            for (int c = 0; c < 4; c++) acc1[nt][c] = 0.f;

        #pragma unroll
        for (int ks = 0; ks < 2; ks++) {
            uint32_t ah[4], al[4];
            uint32_t aaddr = su + (uint32_t)((m0 + a_row) * XS + ks * 32 + a_koff);
            ldsm4(ah[0], ah[1], ah[2], ah[3], aaddr + OFF_XHI);
            ldsm4(al[0], al[1], al[2], al[3], aaddr + OFF_XLO);
            #pragma unroll
            for (int ntp = 0; ntp < 4; ntp++) {
                uint32_t bh[4];
                uint32_t baddr = su + (uint32_t)((16 * ntp + b_nrow) * B1S + ks * 32 + b_koff);
                ldsm4(bh[0], bh[1], bh[2], bh[3], baddr + OFF_B1);
                mma16816(acc1[2 * ntp],     ah, bh[0], bh[1]);
                mma16816(acc1[2 * ntp + 1], ah, bh[2], bh[3]);
                mma16816(acc1[2 * ntp],     al, bh[0], bh[1]);
                mma16816(acc1[2 * ntp + 1], al, bh[2], bh[3]);
            }
        }

        // ---- H = relu(+b1) -> fp16 single into smem (own rows only) ----
        #pragma unroll
        for (int nt = 0; nt < 8; nt++) {
            int j = 8 * nt + 2 * tig;
            float bb0 = sb1[j], bb1 = sb1[j + 1];
            *(uint32_t*)(smem + OFF_HHI + (m0 + g) * HS + j * 2) =
                pack2(fmaxf(acc1[nt][0] + bb0, 0.f), fmaxf(acc1[nt][1] + bb1, 0.f));
            *(uint32_t*)(smem + OFF_HHI + (m0 + g + 8) * HS + j * 2) =
                pack2(fmaxf(acc1[nt][2] + bb0, 0.f), fmaxf(acc1[nt][3] + bb1, 0.f));
        }
        __syncwarp();

        // ---- hoist GEMM2 A-fragments (fp16 single, reused for both n-halves) ----
        uint32_t Ah[4][4];
        #pragma unroll
        for (int ks = 0; ks < 4; ks++) {
            uint32_t aaddr = su + (uint32_t)((m0 + a_row) * HS + ks * 32 + a_koff);
            ldsm4(Ah[ks][0], Ah[ks][1], Ah[ks][2], Ah[ks][3], aaddr + OFF_HHI);
        }

        // ================ GEMM2 (two 64-col halves) + per-warp epilogue ================
        #pragma unroll 1
        for (int nh = 0; nh < 2; nh++) {
            float acc[8][4];
            #pragma unroll
            for (int nt = 0; nt < 8; nt++)
                #pragma unroll
                for (int c = 0; c < 4; c++) acc[nt][c] = 0.f;

            #pragma unroll
            for (int ks = 0; ks < 4; ks++) {
                #pragma unroll
                for (int ntp = 0; ntp < 4; ntp++) {
                    int nrow = 64 * nh + 16 * ntp;
                    uint32_t bh[4];
                    uint32_t baddr = su + (uint32_t)((nrow + b_nrow) * HS + ks * 32 + b_koff);
                    ldsm4(bh[0], bh[1], bh[2], bh[3], baddr + OFF_B2);
                    mma16816(acc[2 * ntp],     Ah[ks], bh[0], bh[1]);
                    mma16816(acc[2 * ntp + 1], Ah[ks], bh[2], bh[3]);
                }
            }

            // per-warp epilogue: 2 passes of 32 cols through warp-private O staging
            #pragma unroll 1
            for (int p = 0; p < 2; p++) {
                __syncwarp();
                #pragma unroll
                for (int q = 0; q < 4; q++) {
                    int nt = 4 * p + q;
                    int cl = 8 * q + 2 * tig;
                    int jg = 64 * nh + 32 * p + cl;
                    float bb0 = sb2[jg], bb1 = sb2[jg + 1];
                    float* rA = OW + g * O_PITCH + cl;
                    rA[0] = fmaxf(acc[nt][0] + bb0, 0.f);
                    rA[1] = fmaxf(acc[nt][1] + bb1, 0.f);
                    float* rB = OW + (g + 8) * O_PITCH + cl;
                    rB[0] = fmaxf(acc[nt][2] + bb0, 0.f);
                    rB[1] = fmaxf(acc[nt][3] + bb1, 0.f);
                }
                __syncwarp();
                {   // run-length segment max: lane = 1 col x this warp's 16 sorted rows
                    int j = 64 * nh + 32 * p + lane;
                    const float* ocol = OW + lane;
                    float rm = 0.f; int cs = -1;
                    #pragma unroll
                    for (int mi = 0; mi < 16; mi++) {
                        int s = ssg[m0 + mi];
                        float v = ocol[mi * O_PITCH];
                        if (s != cs) {
                            if (cs >= 0) {
                                unsigned u = __float_as_uint(rm);  // >=0: bit order == fp order
                                if (u) atomicMax(out + (size_t)cs * ED + j, u);
                            }
                            cs = s; rm = v;
                        } else rm = fmaxf(rm, v);
                    }
                    if (cs >= 0) {
                        unsigned u = __float_as_uint(rm);
                        if (u) atomicMax(out + (size_t)cs * ED + j, u);
                    }
                }
            }
        }
        __syncwarp();   // staging regions quiesced before next tile
    }
}

extern "C" void kernel_launch(void* const* d_in, const int* in_sizes, int n_in,
                              void* d_out, int out_size)
{
    const float* X   = (const float*)d_in[0];
    const int*   seg = (const int*)  d_in[1];
    const float* W1  = (const float*)d_in[2];
    const float* b1  = (const float*)d_in[3];
    const float* W2  = (const float*)d_in[4];
    const float* b2  = (const float*)d_in[5];
    float* out = (float*)d_out;

    int n = in_sizes[1];
    int nseg = out_size / ED;

    cudaFuncSetAttribute(fused_mlp_segmax_mma,
                         cudaFuncAttributeMaxDynamicSharedMemorySize, SMEM_TOTAL);

    int initN = max(out_size, nseg);
    zero_and_init<<<(initN + 255) / 256, 256>>>(out, out_size, nseg);
    hist_kernel<<<(n + 255) / 256, 256>>>(seg, n);
    scan_kernel<<<1, 1024>>>(nseg);
    scatter_kernel<<<(n + 255) / 256, 256>>>(seg, n);

    int tiles = (n + MT - 1) / MT;
    int grid = (tiles + TPC - 1) / TPC;
    fused_mlp_segmax_mma<<<grid, 256, SMEM_TOTAL>>>(X, seg, W1, b1, W2, b2, (unsigned*)out, n);
}